// round 10
// baseline (speedup 1.0000x reference)
#include <cuda_runtime.h>
#include <cuda_bf16.h>
#include <math.h>
#include <cstdint>

#define B 8
#define L 2048
#define D 256
#define NEG_INF -1e10f

// ---------------- device scratch (static, no allocations) ----------------
__device__ __align__(16) uint32_t g_sx[B * L * D / 2];   // hx bf16x2 packed, row-major
__device__ __align__(16) uint32_t g_sy[B * L * D / 2];   // hy bf16x2
__device__ __align__(16) uint32_t g_wt[D * D / 2];       // (log2e * W)^T [n][k] bf16x2
__device__ __align__(16) uint32_t g_pw[B * L * D / 2];   // predW bf16x2 (log2 domain)
__device__ float g_pred_sq[B * L];
__device__ float g_src_sq[B * L];
__device__ float g_rowval[B * L];

// ---------------- generic helpers ----------------
__device__ __forceinline__ uint32_t smem_u32(const void* p) {
    uint32_t a;
    asm("{ .reg .u64 t; cvta.to.shared.u64 t, %1; cvt.u32.u64 %0, t; }" : "=r"(a) : "l"(p));
    return a;
}
__device__ __forceinline__ uint32_t pack_bf16x2(float lo, float hi) {
    uint32_t u;
    asm("cvt.rn.bf16x2.f32 %0, %1, %2;" : "=r"(u) : "f"(hi), "f"(lo));
    return u;
}
__device__ __forceinline__ float2 unpack_bf(uint32_t u) {
    __nv_bfloat162 h = *reinterpret_cast<__nv_bfloat162*>(&u);
    return make_float2(__bfloat162float(h.x), __bfloat162float(h.y));
}
__device__ __forceinline__ float sqrt_fast(float v) {
    float r;
    asm("sqrt.approx.f32 %0, %1;" : "=f"(r) : "f"(v));
    return r;
}
__device__ __forceinline__ float ex2_fast(float v) {
    float r;
    asm("ex2.approx.f32 %0, %1;" : "=f"(r) : "f"(v));
    return r;
}

// Load a [nrows x 256] bf16 tile (packed u32 rows of 128) into SW128 blocked-atom smem.
__device__ __forceinline__ void load_tile_bf16(const uint32_t* __restrict__ g,
                                               char* sm, uint32_t off,
                                               int tid, int nthr, int nrows) {
    const uint4* g4 = (const uint4*)g;
    int total = nrows * 32;            // uint4 per tile
    int ar = nrows >> 3;               // atom-rows
    for (int idx = tid; idx < total; idx += nthr) {
        uint4 v = __ldg(&g4[idx]);
        int r = idx >> 5;
        uint32_t kb = (uint32_t)(idx & 31) * 16u;
        uint32_t boff = (uint32_t)((r >> 3) + (int)(kb >> 7) * ar) * 1024u
                        + (uint32_t)(r & 7) * 128u + (kb & 127u);
        uint32_t sw = boff ^ ((boff >> 3) & 0x70);
        *(uint4*)(sm + off + sw) = v;
    }
}

// ---------------- kernel 1: prep — bf16 convert + fp32 sq-norms ----------------
__global__ void prep_kernel(const float* __restrict__ hx, const float* __restrict__ hy) {
    int gtid = blockIdx.x * blockDim.x + threadIdx.x;
    int row = gtid >> 5;
    int lane = gtid & 31;
    if (row >= B * L) return;
    const float2* xr = (const float2*)(hx + (size_t)row * D);
    const float2* yr = (const float2*)(hy + (size_t)row * D);
    uint32_t* xo = g_sx + (size_t)row * 128;
    uint32_t* yo = g_sy + (size_t)row * 128;
    float sx = 0.f, sy = 0.f;
    #pragma unroll
    for (int j = 0; j < 4; j++) {
        int c = j * 32 + lane;
        float2 vx = xr[c];
        sx += vx.x * vx.x + vx.y * vx.y;
        xo[c] = pack_bf16x2(vx.x, vx.y);
        float2 vy = yr[c];
        sy += vy.x * vy.x + vy.y * vy.y;
        yo[c] = pack_bf16x2(vy.x, vy.y);
    }
    #pragma unroll
    for (int o = 16; o > 0; o >>= 1) {
        sx += __shfl_down_sync(0xffffffffu, sx, o);
        sy += __shfl_down_sync(0xffffffffu, sy, o);
    }
    if (lane == 0) { g_src_sq[row] = sx; g_pred_sq[row] = sy; }
}

// ---------------- kernel 2: W transpose -> bf16 [n][k], scaled by log2(e) ------
__global__ void wt_kernel(const float* __restrict__ W) {
    const float LOG2E = 1.4426950408889634f;
    int n = blockIdx.x;
    int t = threadIdx.x;
    float a = W[(size_t)(2 * t) * D + n] * LOG2E;
    float b = W[(size_t)(2 * t + 1) * D + n] * LOG2E;
    g_wt[n * 128 + t] = pack_bf16x2(a, b);
}

// ---------------- tcgen05 machinery (sm_103a-only) ----------------
static constexpr uint64_t DESC_BASE_SW128 =
    (uint64_t(2) << 61) | (uint64_t(1) << 46) | (uint64_t(64) << 32) | (uint64_t(1) << 16);
#define MK_DESC(a) (DESC_BASE_SW128 | ((uint64_t)((a) >> 4) & 0x3FFF))
static constexpr uint32_t IDESC_BF16_N128 =
    (1u << 4) | (1u << 7) | (1u << 10) | (16u << 17) | (8u << 24);
static constexpr uint32_t IDESC_BF16_N64 =
    (1u << 4) | (1u << 7) | (1u << 10) | (8u << 17) | (8u << 24);

#if defined(__CUDA_ARCH_SPECIFIC__)
#define TC_ALLOC(sm, n)   asm volatile("tcgen05.alloc.cta_group::1.sync.aligned.shared::cta.b32 [%0], %1;" :: "r"(sm), "r"(n) : "memory")
#define TC_DEALLOC(t, n)  asm volatile("tcgen05.dealloc.cta_group::1.sync.aligned.b32 %0, %1;" :: "r"(t), "r"(n))
#define TC_RELINQ()       asm volatile("tcgen05.relinquish_alloc_permit.cta_group::1.sync.aligned;")
#define TC_COMMIT(mb)     asm volatile("tcgen05.commit.cta_group::1.mbarrier::arrive::one.shared::cluster.b64 [%0];" :: "r"(mb) : "memory")
#define TC_FENCE_AFTER()  asm volatile("tcgen05.fence::after_thread_sync;" ::: "memory")
#define TC_WAIT_LD()      asm volatile("tcgen05.wait::ld.sync.aligned;" ::: "memory")
#define MBAR_INIT(mb, c)  asm volatile("mbarrier.init.shared.b64 [%0], %1;" :: "r"(mb), "r"(c) : "memory")
#define MBAR_INVAL(mb)    asm volatile("mbarrier.inval.shared.b64 [%0];" :: "r"(mb) : "memory")
#define MBAR_ARRIVE(mb)   asm volatile("mbarrier.arrive.shared.b64 _, [%0];" :: "r"(mb) : "memory")
#define FENCE_ASYNC()     asm volatile("fence.proxy.async.shared::cta;" ::: "memory")

#define MBAR_WAIT(mb, par) do {                                                        \
    uint32_t _m = (mb), _p = (par), _d;                                                \
    asm volatile("{\n\t.reg .pred p;\n\t"                                              \
        "mbarrier.try_wait.parity.acquire.cta.shared::cta.b64 p, [%1], %2;\n\t"        \
        "selp.b32 %0, 1, 0, p;\n\t}" : "=r"(_d) : "r"(_m), "r"(_p) : "memory");        \
    if (!_d) {                                                                          \
        asm volatile("{\n\t.reg .pred P1;\n\tWL_%=:\n\t"                               \
            "mbarrier.try_wait.parity.acquire.cta.shared::cta.b64 P1, [%0], %1, 0x989680;\n\t" \
            "@P1 bra.uni WD_%=;\n\tbra.uni WL_%=;\n\tWD_%=:\n\t}"                      \
            :: "r"(_m), "r"(_p) : "memory");                                            \
    } } while (0)

#define LDTM32(r, addr)                                                                \
    asm volatile("tcgen05.ld.sync.aligned.32x32b.x32.b32 "                             \
        "{%0,%1,%2,%3,%4,%5,%6,%7,%8,%9,%10,%11,%12,%13,%14,%15,"                      \
        "%16,%17,%18,%19,%20,%21,%22,%23,%24,%25,%26,%27,%28,%29,%30,%31}, [%32];"     \
        : "=r"((r)[0]),"=r"((r)[1]),"=r"((r)[2]),"=r"((r)[3]),                          \
          "=r"((r)[4]),"=r"((r)[5]),"=r"((r)[6]),"=r"((r)[7]),                          \
          "=r"((r)[8]),"=r"((r)[9]),"=r"((r)[10]),"=r"((r)[11]),                        \
          "=r"((r)[12]),"=r"((r)[13]),"=r"((r)[14]),"=r"((r)[15]),                      \
          "=r"((r)[16]),"=r"((r)[17]),"=r"((r)[18]),"=r"((r)[19]),                      \
          "=r"((r)[20]),"=r"((r)[21]),"=r"((r)[22]),"=r"((r)[23]),                      \
          "=r"((r)[24]),"=r"((r)[25]),"=r"((r)[26]),"=r"((r)[27]),                      \
          "=r"((r)[28]),"=r"((r)[29]),"=r"((r)[30]),"=r"((r)[31])                       \
        : "r"(addr))

__device__ __forceinline__ uint32_t elect_one() {
    uint32_t pred;
    asm volatile("{\n\t.reg .pred p;\n\telect.sync _|p, 0xFFFFFFFF;\n\tselp.b32 %0, 1, 0, p;\n\t}" : "=r"(pred));
    return pred;
}
__device__ __forceinline__ void mma_bf16_n128(uint32_t d, uint64_t a, uint64_t b, uint32_t en) {
    asm volatile(
        "{\n\t.reg .pred p;\n\tsetp.ne.u32 p, %4, 0;\n\t"
        "tcgen05.mma.cta_group::1.kind::f16 [%0], %1, %2, %3, {%5,%5,%5,%5}, p;\n\t}"
        :: "r"(d), "l"(a), "l"(b), "r"(IDESC_BF16_N128), "r"(en), "r"(0u)
        : "memory");
}
__device__ __forceinline__ void mma_bf16_n64(uint32_t d, uint64_t a, uint64_t b, uint32_t en) {
    asm volatile(
        "{\n\t.reg .pred p;\n\tsetp.ne.u32 p, %4, 0;\n\t"
        "tcgen05.mma.cta_group::1.kind::f16 [%0], %1, %2, %3, {%5,%5,%5,%5}, p;\n\t}"
        :: "r"(d), "l"(a), "l"(b), "r"(IDESC_BF16_N64), "r"(en), "r"(0u)
        : "memory");
}
#endif  // __CUDA_ARCH_SPECIFIC__

// ---------------- kernel 3: predW via tcgen05 ----------------
#define PW_A   0u
#define PW_WT  65536u
#define PW_PTR 196608u
#define PW_MB  196624u
#define PW_SMEM 196640

__global__ void __launch_bounds__(128, 1) predw_kernel() {
    extern __shared__ char smem[];
    int tid = threadIdx.x;
    int m0 = blockIdx.x * 128;
#if defined(__CUDA_ARCH_SPECIFIC__)
    uint32_t sbase = smem_u32(smem);
    int wid = tid >> 5;
    if (wid == 0) { TC_ALLOC(sbase + PW_PTR, 256); TC_RELINQ(); }
    if (tid == 0) MBAR_INIT(sbase + PW_MB, 1);

    load_tile_bf16(g_sy + (size_t)m0 * 128, smem, PW_A, tid, 128, 128);
    load_tile_bf16(g_wt, smem, PW_WT, tid, 128, 256);
    FENCE_ASYNC();
    __syncthreads();

    uint32_t tmem;
    asm volatile("ld.shared.b32 %0, [%1];" : "=r"(tmem) : "r"(sbase + PW_PTR));

    if (wid == 0 && elect_one()) {
        uint64_t ad = MK_DESC(sbase + PW_A);
        uint64_t bd = MK_DESC(sbase + PW_WT);
        #pragma unroll
        for (int ks = 0; ks < 16; ks++) {
            uint64_t oa = (uint64_t)((ks >> 2) * 1024 + (ks & 3) * 2);
            uint64_t ob = (uint64_t)((ks >> 2) * 2048 + (ks & 3) * 2);
            uint32_t en = ks > 0 ? 1u : 0u;
            mma_bf16_n128(tmem + 0,   ad + oa, bd + ob,        en);
            mma_bf16_n128(tmem + 128, ad + oa, bd + ob + 1024, en);
        }
        TC_COMMIT(sbase + PW_MB);
    }
    __syncthreads();
    MBAR_WAIT(sbase + PW_MB, 0u);
    TC_FENCE_AFTER();

    uint32_t* stage = (uint32_t*)smem;
    #pragma unroll 1
    for (int cb = 0; cb < 8; cb++) {
        uint32_t r[32];
        LDTM32(r, tmem + cb * 32);
        TC_WAIT_LD();
        #pragma unroll
        for (int j = 0; j < 16; j++)
            stage[tid * 132 + cb * 16 + j] =
                pack_bf16x2(__uint_as_float(r[2 * j]), __uint_as_float(r[2 * j + 1]));
    }
    __syncthreads();
    uint32_t* gout = g_pw + (size_t)m0 * 128;
    #pragma unroll 8
    for (int i = 0; i < 128; i++) {
        int idx = tid + i * 128;
        gout[idx] = stage[(idx >> 7) * 132 + (idx & 127)];
    }
    __syncthreads();
    if (tid == 0) MBAR_INVAL(sbase + PW_MB);
    __syncthreads();
    if (wid == 0) TC_DEALLOC(tmem, 256);
#else
    for (int n = tid; n < D; n += 128) {
        int row = m0;
        float2 a0 = unpack_bf(g_sy[(size_t)row * 128]);
        float2 w0 = unpack_bf(g_wt[n * 128]);
        g_pw[(size_t)row * 128 + n / 2] = pack_bf16x2(a0.x * w0.x, a0.y * w0.y);
    }
#endif
}

// ---------------- kernel 4: warp-specialized fused kernel --------------------
// 384 threads: warps 0-7 consumers, warps 8-11 producers.
// Producer: subtile-granular (64 s-cols), smem ring-2, TMEM ring-4 x 128 cols
// (cross @+0..63, tr @+64..127 per subtile buffer), commit per subtile.
// Consumer: waits once per PAIR (odd commit covers both), software-pipelines
// LDTM of subtile B behind math of subtile A.
#define F_P     0u
#define F_Q     65536u
#define F_S     131072u      // 2 x 32768 smem ring
#define F_SSQ   196608u      // 2048 f32
#define F_SMK   204800u      // 2048 f32
#define F_ANYV  212992u      // 32 u32
#define F_ALLV  213120u      // 32 u32
#define F_MODE  213248u
#define F_PTR   213260u
#define F_MBF   213264u      // full[4]
#define F_MBE   213296u      // empty[4]
#define F_CMB   213328u      // 2*256 f32 (Z, Nv)
#define F_SMEM  215392

#define MODE_FAST 0
#define MODE_UNIF 1
#define MODE_GEN  2

__global__ void __launch_bounds__(384, 1) fused_kernel(
    const float* __restrict__ xmask, const float* __restrict__ ymask) {
    extern __shared__ char smem[];
    int tid = threadIdx.x;
    int b = blockIdx.x >> 4;
    int p0 = (blockIdx.x & 15) * 128;
#if defined(__CUDA_ARCH_SPECIFIC__)
    uint32_t sbase = smem_u32(smem);
    int wid = tid >> 5;
    int lane = tid & 31;

    if (wid == 0) { TC_ALLOC(sbase + F_PTR, 512); TC_RELINQ(); }
    if (tid == 0) {
        #pragma unroll
        for (int k = 0; k < 4; k++) {
            MBAR_INIT(sbase + F_MBF + k * 8, 1);   // full: 1 commit per subtile
            MBAR_INIT(sbase + F_MBE + k * 8, 8);   // empty: 1 arrive per consumer warp
        }
    }

    float* s_ssq  = (float*)(smem + F_SSQ);
    float* s_smk  = (float*)(smem + F_SMK);
    uint32_t* s_anyv = (uint32_t*)(smem + F_ANYV);
    uint32_t* s_allv = (uint32_t*)(smem + F_ALLV);
    uint32_t* s_mode = (uint32_t*)(smem + F_MODE);

    for (int i = tid; i < L; i += 384) {
        s_ssq[i] = g_src_sq[b * L + i];
        s_smk[i] = xmask[b * L + i];
    }
    int cnt = __syncthreads_count((tid < 128) ? (ymask[b * L + p0 + tid] != 0.f) : 0);
    if (tid < 32) {
        float fa = 0.f, fl = 1.f;
        #pragma unroll 8
        for (int i = 0; i < 64; i++) {
            float v = s_smk[tid * 64 + i];
            fa = fmaxf(fa, v);
            fl = fminf(fl, (v != 0.f) ? 1.f : 0.f);
        }
        s_anyv[tid] = (fa != 0.f) ? 1u : 0u;
        s_allv[tid] = (fl != 0.f) ? 1u : 0u;
        unsigned anyb = __ballot_sync(0xffffffffu, fa != 0.f);
        if (tid == 0)
            s_mode[0] = (cnt == 0 || anyb == 0) ? MODE_UNIF
                       : (cnt == 128 ? MODE_FAST : MODE_GEN);
    }
    __syncthreads();
    uint32_t mode = s_mode[0];

    load_tile_bf16(g_sy + ((size_t)b * L + p0) * 128, smem, F_P, tid, 384, 128);
    if (mode != MODE_UNIF)
        load_tile_bf16(g_pw + ((size_t)b * L + p0) * 128, smem, F_Q, tid, 384, 128);
    FENCE_ASYNC();
    __syncthreads();

    uint32_t tmem;
    asm volatile("ld.shared.b32 %0, [%1];" : "=r"(tmem) : "r"(sbase + F_PTR));

    if (tid < 256) {
        // ---------------- consumers (8 warps) ----------------
        int sp = wid & 3;
        int half = wid >> 2;
        int row = sp * 32 + lane;
        float psq = g_pred_sq[b * L + p0 + row];
        float pm  = ymask[b * L + p0 + row];
        bool pmz = (pm == 0.f);
        float Z = 0.f, Nv = 0.f;

        int k = 0;   // kept-pair counter
        #pragma unroll 1
        for (int jp = 0; jp < 16; jp++) {
            if (mode == MODE_FAST && !(s_anyv[2 * jp] | s_anyv[2 * jp + 1])) continue;
            int sA = 2 * k, sB = 2 * k + 1;           // subtile counters
            MBAR_WAIT(sbase + F_MBF + (uint32_t)(sB & 3) * 8, (uint32_t)((sB >> 2) & 1));
            TC_FENCE_AFTER();
            uint32_t bufA = tmem + (uint32_t)(sA & 3) * 128u + (uint32_t)(half * 32);
            uint32_t bufB = tmem + (uint32_t)(sB & 3) * 128u + (uint32_t)(half * 32);
            int jA = 2 * jp, jB = 2 * jp + 1;
            int sbA = jA * 64 + half * 32;
            int sbB = jB * 64 + half * 32;
            if (mode == MODE_UNIF) {
                uint32_t cA[32], cB[32];
                LDTM32(cA, bufA);
                LDTM32(cB, bufB);
                TC_WAIT_LD();
                if (lane == 0) {
                    MBAR_ARRIVE(sbase + F_MBE + (uint32_t)(sA & 3) * 8);
                    MBAR_ARRIVE(sbase + F_MBE + (uint32_t)(sB & 3) * 8);
                }
                float na[4] = {0.f, 0.f, 0.f, 0.f};
                #pragma unroll
                for (int jj = 0; jj < 32; jj++) {
                    float d2 = fmaxf(fmaf(-2.f, __uint_as_float(cA[jj]),
                                          psq + s_ssq[sbA + jj]), 0.f);
                    na[jj & 3] += sqrt_fast(d2);
                }
                #pragma unroll
                for (int jj = 0; jj < 32; jj++) {
                    float d2 = fmaxf(fmaf(-2.f, __uint_as_float(cB[jj]),
                                          psq + s_ssq[sbB + jj]), 0.f);
                    na[jj & 3] += sqrt_fast(d2);
                }
                Nv += (na[0] + na[1]) + (na[2] + na[3]);
            } else {
                uint32_t cxA[32], trA[32];
                LDTM32(cxA, bufA);
                LDTM32(trA, bufA + 64u);
                TC_WAIT_LD();
                if (lane == 0) MBAR_ARRIVE(sbase + F_MBE + (uint32_t)(sA & 3) * 8);
                // issue B's TMEM reads now; math A overlaps their service
                uint32_t cxB[32], trB[32];
                LDTM32(cxB, bufB);
                LDTM32(trB, bufB + 64u);
                {   // math subtile A
                    float za[4] = {0.f, 0.f, 0.f, 0.f}, na[4] = {0.f, 0.f, 0.f, 0.f};
                    if (mode == MODE_FAST && s_allv[jA]) {
                        #pragma unroll
                        for (int jj = 0; jj < 32; jj++) {
                            float d2 = fmaxf(fmaf(-2.f, __uint_as_float(cxA[jj]),
                                                  psq + s_ssq[sbA + jj]), 0.f);
                            float cc = sqrt_fast(d2);
                            float e = ex2_fast(fminf(__uint_as_float(trA[jj]), 100.f));
                            za[jj & 3] += e;
                            na[jj & 3] = fmaf(e, cc, na[jj & 3]);
                        }
                    } else {
                        #pragma unroll
                        for (int jj = 0; jj < 32; jj++) {
                            float d2 = fmaxf(fmaf(-2.f, __uint_as_float(cxA[jj]),
                                                  psq + s_ssq[sbA + jj]), 0.f);
                            float cc = sqrt_fast(d2);
                            float e = ex2_fast(fminf(__uint_as_float(trA[jj]), 100.f));
                            e = (s_smk[sbA + jj] != 0.f) ? e : 0.f;
                            e = pmz ? 1.f : e;
                            za[jj & 3] += e;
                            na[jj & 3] = fmaf(e, cc, na[jj & 3]);
                        }
                    }
                    Z  += (za[0] + za[1]) + (za[2] + za[3]);
                    Nv += (na[0] + na[1]) + (na[2] + na[3]);
                }
                TC_WAIT_LD();
                if (lane == 0) MBAR_ARRIVE(sbase + F_MBE + (uint32_t)(sB & 3) * 8);
                {   // math subtile B
                    float za[4] = {0.f, 0.f, 0.f, 0.f}, na[4] = {0.f, 0.f, 0.f, 0.f};
                    if (mode == MODE_FAST && s_allv[jB]) {
                        #pragma unroll
                        for (int jj = 0; jj < 32; jj++) {
                            float d2 = fmaxf(fmaf(-2.f, __uint_as_float(cxB[jj]),
                                                  psq + s_ssq[sbB + jj]), 0.f);
                            float cc = sqrt_fast(d2);
                            float e = ex2_fast(fminf(__uint_as_float(trB[jj]), 100.f));
                            za[jj & 3] += e;
                            na[jj & 3] = fmaf(e, cc, na[jj & 3]);
                        }
                    } else {
                        #pragma unroll
                        for (int jj = 0; jj < 32; jj++) {
                            float d2 = fmaxf(fmaf(-2.f, __uint_as_float(cxB[jj]),
                                                  psq + s_ssq[sbB + jj]), 0.f);
                            float cc = sqrt_fast(d2);
                            float e = ex2_fast(fminf(__uint_as_float(trB[jj]), 100.f));
                            e = (s_smk[sbB + jj] != 0.f) ? e : 0.f;
                            e = pmz ? 1.f : e;
                            za[jj & 3] += e;
                            na[jj & 3] = fmaf(e, cc, na[jj & 3]);
                        }
                    }
                    Z  += (za[0] + za[1]) + (za[2] + za[3]);
                    Nv += (na[0] + na[1]) + (na[2] + na[3]);
                }
            }
            k++;
        }
        if (mode == MODE_UNIF) Z = 1024.f;   // 64 cols x 16 pairs per warp
        float* cm = (float*)(smem + F_CMB);
        cm[tid] = Z; cm[256 + tid] = Nv;
    } else {
        // ---------------- producers (warps 8-11) ----------------
        int ptid = tid - 256;
        uint64_t pd = MK_DESC(sbase + F_P);
        uint64_t qd = MK_DESC(sbase + F_Q);
        int it = 0;   // kept-subtile counter
        #pragma unroll 1
        for (int jp = 0; jp < 16; jp++) {
            if (mode == MODE_FAST && !(s_anyv[2 * jp] | s_anyv[2 * jp + 1])) continue;
            #pragma unroll 1
            for (int hh = 0; hh < 2; hh++) {
                int j = 2 * jp + hh;
                if (it >= 2)    // smem ring-2: MMA of subtile it-2 must be done
                    MBAR_WAIT(sbase + F_MBF + (uint32_t)((it - 2) & 3) * 8,
                              (uint32_t)(((it - 2) >> 2) & 1));
                load_tile_bf16(g_sx + ((size_t)b * L + j * 64) * 128, smem,
                               F_S + (uint32_t)(it & 1) * 32768u, ptid, 128, 64);
                FENCE_ASYNC();
                asm volatile("bar.sync 1, 128;" ::: "memory");
                if (wid == 8) {
                    if (it >= 4)   // TMEM ring-4: consumers drained subtile it-4
                        MBAR_WAIT(sbase + F_MBE + (uint32_t)(it & 3) * 8,
                                  (uint32_t)(((it >> 2) - 1) & 1));
                    if (elect_one()) {
                        uint64_t sd = MK_DESC(sbase + F_S + (uint32_t)(it & 1) * 32768u);
                        uint32_t dbase = tmem + (uint32_t)(it & 3) * 128u;
                        if (mode == MODE_UNIF) {
                            #pragma unroll
                            for (int ks = 0; ks < 16; ks++) {
                                uint64_t oa = (uint64_t)((ks >> 2) * 1024 + (ks & 3) * 2);
                                uint64_t ob = (uint64_t)((ks >> 2) * 512 + (ks & 3) * 2);
                                mma_bf16_n64(dbase, pd + oa, sd + ob, ks > 0 ? 1u : 0u);
                            }
                        } else {
                            #pragma unroll
                            for (int ks = 0; ks < 16; ks++) {
                                uint64_t oa = (uint64_t)((ks >> 2) * 1024 + (ks & 3) * 2);
                                uint64_t ob = (uint64_t)((ks >> 2) * 512 + (ks & 3) * 2);
                                uint32_t en = ks > 0 ? 1u : 0u;
                                mma_bf16_n64(dbase + 0,  pd + oa, sd + ob, en);
                                mma_bf16_n64(dbase + 64, qd + oa, sd + ob, en);
                            }
                        }
                        TC_COMMIT(sbase + F_MBF + (uint32_t)(it & 3) * 8);
                    }
                }
                it++;
            }
        }
    }
    __syncthreads();

    // combine halves: row r partials at cm[r] and cm[r+128]
    if (tid < 128) {
        float* cm = (float*)(smem + F_CMB);
        float Zt = cm[tid] + cm[tid + 128];
        float Nt = cm[256 + tid] + cm[256 + tid + 128];
        g_rowval[b * L + p0 + tid] = Nt / Zt;
    }
    __syncthreads();
    if (tid == 0) {
        #pragma unroll
        for (int k2 = 0; k2 < 4; k2++) {
            MBAR_INVAL(sbase + F_MBF + k2 * 8);
            MBAR_INVAL(sbase + F_MBE + k2 * 8);
        }
    }
    __syncthreads();
    if (wid == 0) TC_DEALLOC(tmem, 512);
#else
    // dead generic-PTX fallback (GB300 always loads the sm_103a cubin)
    if (tid < 128) {
        int p = p0 + tid;
        float psq = g_pred_sq[b * L + p];
        float pm  = ymask[b * L + p];
        float Z = 0.f, Nv = 0.f;
        for (int s = 0; s < L; s++) {
            float cross = 0.f, tvv = 0.f;
            for (int kk = 0; kk < 128; kk++) {
                float2 a = unpack_bf(g_sy[((size_t)b * L + p) * 128 + kk]);
                float2 qv = unpack_bf(g_pw[((size_t)b * L + p) * 128 + kk]);
                float2 s2 = unpack_bf(g_sx[((size_t)b * L + s) * 128 + kk]);
                cross += a.x * s2.x + a.y * s2.y;
                tvv += qv.x * s2.x + qv.y * s2.y;
            }
            float c = sqrtf(fmaxf(psq + g_src_sq[b * L + s] - 2.f * cross, 0.f));
            float e;
            if (pm == 0.f) e = 1.f;
            else e = (xmask[b * L + s] != 0.f) ? exp2f(fminf(tvv, 100.f)) : 0.f;
            Z += e;
            Nv += e * c;
        }
        g_rowval[b * L + p] = Nv / Z;
    }
#endif
}

// ---------------- kernel 5: deterministic final reduction ----------------
__global__ void finalize_kernel(const float* __restrict__ xmask,
                                const float* __restrict__ ymask,
                                float* __restrict__ out) {
    __shared__ float red[256];
    __shared__ float inv[B];
    int tid = threadIdx.x;
    int warp = tid >> 5;
    int lane = tid & 31;
    float n1 = 0.f, n2 = 0.f;
    for (int i = lane; i < L; i += 32) {
        n1 += ymask[warp * L + i];
        n2 += xmask[warp * L + i];
    }
    #pragma unroll
    for (int o = 16; o > 0; o >>= 1) {
        n1 += __shfl_down_sync(0xffffffffu, n1, o);
        n2 += __shfl_down_sync(0xffffffffu, n2, o);
    }
    if (lane == 0) inv[warp] = 1.f / (n1 * n2);

    float s = 0.f;
    for (int i = tid; i < B * L; i += 256) s += g_rowval[i];
    red[tid] = s;
    __syncthreads();
    for (int o = 128; o > 0; o >>= 1) {
        if (tid < o) red[tid] += red[tid + o];
        __syncthreads();
    }
    if (tid == 0) {
        float F = 0.f;
        for (int bb = 0; bb < B; bb++) F += inv[bb];
        out[0] = red[0] * F / (float)(B * B);
    }
}

// ---------------- launch ----------------
extern "C" void kernel_launch(void* const* d_in, const int* in_sizes, int n_in,
                              void* d_out, int out_size) {
    const float* hx = (const float*)d_in[0];
    const float* hy = (const float*)d_in[1];
    const float* xm = (const float*)d_in[2];
    const float* ym = (const float*)d_in[3];
    const float* W  = (const float*)d_in[4];
    float* out = (float*)d_out;

    cudaFuncSetAttribute(predw_kernel,
                         cudaFuncAttributeMaxDynamicSharedMemorySize, PW_SMEM);
    cudaFuncSetAttribute(fused_kernel,
                         cudaFuncAttributeMaxDynamicSharedMemorySize, F_SMEM);

    prep_kernel<<<(B * L * 32 + 255) / 256, 256>>>(hx, hy);
    wt_kernel<<<D, 128>>>(W);
    predw_kernel<<<(B * L) / 128, 128, PW_SMEM>>>();
    fused_kernel<<<B * (L / 128), 384, F_SMEM>>>(xm, ym);
    finalize_kernel<<<1, 256>>>(xm, ym, out);
}

// round 12
// speedup vs baseline: 1.4373x; 1.4373x over previous
#include <cuda_runtime.h>
#include <cuda_bf16.h>
#include <math.h>
#include <cstdint>

#define B 8
#define L 2048
#define D 256
#define NEG_INF -1e10f

// ---------------- device scratch (static, no allocations) ----------------
__device__ __align__(16) uint32_t g_sx[B * L * D / 2];   // hx bf16x2 packed, row-major
__device__ __align__(16) uint32_t g_sy[B * L * D / 2];   // hy bf16x2
__device__ __align__(16) uint32_t g_wt[D * D / 2];       // (log2e * W)^T [n][k] bf16x2
__device__ __align__(16) uint32_t g_pw[B * L * D / 2];   // predW bf16x2 (log2 domain)
__device__ float g_pred_sq[B * L];
__device__ float g_src_sq[B * L];
__device__ float g_rowval[B * L];

// ---------------- generic helpers ----------------
__device__ __forceinline__ uint32_t smem_u32(const void* p) {
    uint32_t a;
    asm("{ .reg .u64 t; cvta.to.shared.u64 t, %1; cvt.u32.u64 %0, t; }" : "=r"(a) : "l"(p));
    return a;
}
__device__ __forceinline__ uint32_t pack_bf16x2(float lo, float hi) {
    uint32_t u;
    asm("cvt.rn.bf16x2.f32 %0, %1, %2;" : "=r"(u) : "f"(hi), "f"(lo));
    return u;
}
__device__ __forceinline__ float2 unpack_bf(uint32_t u) {
    __nv_bfloat162 h = *reinterpret_cast<__nv_bfloat162*>(&u);
    return make_float2(__bfloat162float(h.x), __bfloat162float(h.y));
}
__device__ __forceinline__ float sqrt_fast(float v) {
    float r;
    asm("sqrt.approx.f32 %0, %1;" : "=f"(r) : "f"(v));
    return r;
}
__device__ __forceinline__ float ex2_fast(float v) {
    float r;
    asm("ex2.approx.f32 %0, %1;" : "=f"(r) : "f"(v));
    return r;
}

// ---- cp.async 16B into swizzled smem ----
__device__ __forceinline__ void cp16(uint32_t saddr, const void* gptr) {
    asm volatile("cp.async.cg.shared.global [%0], [%1], 16;"
                 :: "r"(saddr), "l"(gptr) : "memory");
}
#define CP_COMMIT() asm volatile("cp.async.commit_group;" ::: "memory")
#define CP_WAIT0()  asm volatile("cp.async.wait_group 0;" ::: "memory")

// Async-load a [nrows x 256] bf16 tile into SW128 blocked-atom smem (no wait).
__device__ __forceinline__ void load_tile_cp(const uint32_t* __restrict__ g,
                                             uint32_t sm_u32, uint32_t off,
                                             int tid, int nthr, int nrows) {
    const uint4* g4 = (const uint4*)g;
    int total = nrows * 32;            // uint4 per tile
    int ar = nrows >> 3;               // atom-rows
    for (int idx = tid; idx < total; idx += nthr) {
        int r = idx >> 5;
        uint32_t kb = (uint32_t)(idx & 31) * 16u;
        uint32_t boff = (uint32_t)((r >> 3) + (int)(kb >> 7) * ar) * 1024u
                        + (uint32_t)(r & 7) * 128u + (kb & 127u);
        uint32_t sw = boff ^ ((boff >> 3) & 0x70);
        cp16(sm_u32 + off + sw, g4 + idx);
    }
}

// Synchronous variant (register path) kept for predw kernel.
__device__ __forceinline__ void load_tile_bf16(const uint32_t* __restrict__ g,
                                               char* sm, uint32_t off,
                                               int tid, int nthr, int nrows) {
    const uint4* g4 = (const uint4*)g;
    int total = nrows * 32;
    int ar = nrows >> 3;
    for (int idx = tid; idx < total; idx += nthr) {
        uint4 v = __ldg(&g4[idx]);
        int r = idx >> 5;
        uint32_t kb = (uint32_t)(idx & 31) * 16u;
        uint32_t boff = (uint32_t)((r >> 3) + (int)(kb >> 7) * ar) * 1024u
                        + (uint32_t)(r & 7) * 128u + (kb & 127u);
        uint32_t sw = boff ^ ((boff >> 3) & 0x70);
        *(uint4*)(sm + off + sw) = v;
    }
}

// ---------------- kernel 1: prep — bf16 convert + fp32 sq-norms ----------------
__global__ void prep_kernel(const float* __restrict__ hx, const float* __restrict__ hy) {
    int gtid = blockIdx.x * blockDim.x + threadIdx.x;
    int row = gtid >> 5;
    int lane = gtid & 31;
    if (row >= B * L) return;
    const float2* xr = (const float2*)(hx + (size_t)row * D);
    const float2* yr = (const float2*)(hy + (size_t)row * D);
    uint32_t* xo = g_sx + (size_t)row * 128;
    uint32_t* yo = g_sy + (size_t)row * 128;
    float sx = 0.f, sy = 0.f;
    #pragma unroll
    for (int j = 0; j < 4; j++) {
        int c = j * 32 + lane;
        float2 vx = xr[c];
        sx += vx.x * vx.x + vx.y * vx.y;
        xo[c] = pack_bf16x2(vx.x, vx.y);
        float2 vy = yr[c];
        sy += vy.x * vy.x + vy.y * vy.y;
        yo[c] = pack_bf16x2(vy.x, vy.y);
    }
    #pragma unroll
    for (int o = 16; o > 0; o >>= 1) {
        sx += __shfl_down_sync(0xffffffffu, sx, o);
        sy += __shfl_down_sync(0xffffffffu, sy, o);
    }
    if (lane == 0) { g_src_sq[row] = sx; g_pred_sq[row] = sy; }
}

// ---------------- kernel 2: W transpose -> bf16 [n][k], scaled by log2(e) ------
__global__ void wt_kernel(const float* __restrict__ W) {
    const float LOG2E = 1.4426950408889634f;
    int n = blockIdx.x;
    int t = threadIdx.x;
    float a = W[(size_t)(2 * t) * D + n] * LOG2E;
    float b = W[(size_t)(2 * t + 1) * D + n] * LOG2E;
    g_wt[n * 128 + t] = pack_bf16x2(a, b);
}

// ---------------- tcgen05 machinery (sm_103a-only) ----------------
static constexpr uint64_t DESC_BASE_SW128 =
    (uint64_t(2) << 61) | (uint64_t(1) << 46) | (uint64_t(64) << 32) | (uint64_t(1) << 16);
#define MK_DESC(a) (DESC_BASE_SW128 | ((uint64_t)((a) >> 4) & 0x3FFF))
static constexpr uint32_t IDESC_BF16_N128 =
    (1u << 4) | (1u << 7) | (1u << 10) | (16u << 17) | (8u << 24);
static constexpr uint32_t IDESC_BF16_N64 =
    (1u << 4) | (1u << 7) | (1u << 10) | (8u << 17) | (8u << 24);

#if defined(__CUDA_ARCH_SPECIFIC__)
#define TC_ALLOC(sm, n)   asm volatile("tcgen05.alloc.cta_group::1.sync.aligned.shared::cta.b32 [%0], %1;" :: "r"(sm), "r"(n) : "memory")
#define TC_DEALLOC(t, n)  asm volatile("tcgen05.dealloc.cta_group::1.sync.aligned.b32 %0, %1;" :: "r"(t), "r"(n))
#define TC_RELINQ()       asm volatile("tcgen05.relinquish_alloc_permit.cta_group::1.sync.aligned;")
#define TC_COMMIT(mb)     asm volatile("tcgen05.commit.cta_group::1.mbarrier::arrive::one.shared::cluster.b64 [%0];" :: "r"(mb) : "memory")
#define TC_FENCE_AFTER()  asm volatile("tcgen05.fence::after_thread_sync;" ::: "memory")
#define TC_WAIT_LD()      asm volatile("tcgen05.wait::ld.sync.aligned;" ::: "memory")
#define MBAR_INIT(mb, c)  asm volatile("mbarrier.init.shared.b64 [%0], %1;" :: "r"(mb), "r"(c) : "memory")
#define MBAR_INVAL(mb)    asm volatile("mbarrier.inval.shared.b64 [%0];" :: "r"(mb) : "memory")
#define MBAR_ARRIVE(mb)   asm volatile("mbarrier.arrive.shared.b64 _, [%0];" :: "r"(mb) : "memory")
#define FENCE_ASYNC()     asm volatile("fence.proxy.async.shared::cta;" ::: "memory")

#define MBAR_WAIT(mb, par) do {                                                        \
    uint32_t _m = (mb), _p = (par), _d;                                                \
    asm volatile("{\n\t.reg .pred p;\n\t"                                              \
        "mbarrier.try_wait.parity.acquire.cta.shared::cta.b64 p, [%1], %2;\n\t"        \
        "selp.b32 %0, 1, 0, p;\n\t}" : "=r"(_d) : "r"(_m), "r"(_p) : "memory");        \
    if (!_d) {                                                                          \
        asm volatile("{\n\t.reg .pred P1;\n\tWL_%=:\n\t"                               \
            "mbarrier.try_wait.parity.acquire.cta.shared::cta.b64 P1, [%0], %1, 0x989680;\n\t" \
            "@P1 bra.uni WD_%=;\n\tbra.uni WL_%=;\n\tWD_%=:\n\t}"                      \
            :: "r"(_m), "r"(_p) : "memory");                                            \
    } } while (0)

#define LDTM32(r, addr)                                                                \
    asm volatile("tcgen05.ld.sync.aligned.32x32b.x32.b32 "                             \
        "{%0,%1,%2,%3,%4,%5,%6,%7,%8,%9,%10,%11,%12,%13,%14,%15,"                      \
        "%16,%17,%18,%19,%20,%21,%22,%23,%24,%25,%26,%27,%28,%29,%30,%31}, [%32];"     \
        : "=r"((r)[0]),"=r"((r)[1]),"=r"((r)[2]),"=r"((r)[3]),                          \
          "=r"((r)[4]),"=r"((r)[5]),"=r"((r)[6]),"=r"((r)[7]),                          \
          "=r"((r)[8]),"=r"((r)[9]),"=r"((r)[10]),"=r"((r)[11]),                        \
          "=r"((r)[12]),"=r"((r)[13]),"=r"((r)[14]),"=r"((r)[15]),                      \
          "=r"((r)[16]),"=r"((r)[17]),"=r"((r)[18]),"=r"((r)[19]),                      \
          "=r"((r)[20]),"=r"((r)[21]),"=r"((r)[22]),"=r"((r)[23]),                      \
          "=r"((r)[24]),"=r"((r)[25]),"=r"((r)[26]),"=r"((r)[27]),                      \
          "=r"((r)[28]),"=r"((r)[29]),"=r"((r)[30]),"=r"((r)[31])                       \
        : "r"(addr))

__device__ __forceinline__ uint32_t elect_one() {
    uint32_t pred;
    asm volatile("{\n\t.reg .pred p;\n\telect.sync _|p, 0xFFFFFFFF;\n\tselp.b32 %0, 1, 0, p;\n\t}" : "=r"(pred));
    return pred;
}
__device__ __forceinline__ void mma_bf16_n128(uint32_t d, uint64_t a, uint64_t b, uint32_t en) {
    asm volatile(
        "{\n\t.reg .pred p;\n\tsetp.ne.u32 p, %4, 0;\n\t"
        "tcgen05.mma.cta_group::1.kind::f16 [%0], %1, %2, %3, {%5,%5,%5,%5}, p;\n\t}"
        :: "r"(d), "l"(a), "l"(b), "r"(IDESC_BF16_N128), "r"(en), "r"(0u)
        : "memory");
}
__device__ __forceinline__ void mma_bf16_n64(uint32_t d, uint64_t a, uint64_t b, uint32_t en) {
    asm volatile(
        "{\n\t.reg .pred p;\n\tsetp.ne.u32 p, %4, 0;\n\t"
        "tcgen05.mma.cta_group::1.kind::f16 [%0], %1, %2, %3, {%5,%5,%5,%5}, p;\n\t}"
        :: "r"(d), "l"(a), "l"(b), "r"(IDESC_BF16_N64), "r"(en), "r"(0u)
        : "memory");
}
#endif  // __CUDA_ARCH_SPECIFIC__

// ---------------- kernel 3: predW via tcgen05 ----------------
#define PW_A   0u
#define PW_WT  65536u
#define PW_PTR 196608u
#define PW_MB  196624u
#define PW_SMEM 196640

__global__ void __launch_bounds__(128, 1) predw_kernel() {
    extern __shared__ char smem[];
    int tid = threadIdx.x;
    int m0 = blockIdx.x * 128;
#if defined(__CUDA_ARCH_SPECIFIC__)
    uint32_t sbase = smem_u32(smem);
    int wid = tid >> 5;
    if (wid == 0) { TC_ALLOC(sbase + PW_PTR, 256); TC_RELINQ(); }
    if (tid == 0) MBAR_INIT(sbase + PW_MB, 1);

    load_tile_cp(g_sy + (size_t)m0 * 128, sbase, PW_A, tid, 128, 128);
    load_tile_cp(g_wt, sbase, PW_WT, tid, 128, 256);
    CP_COMMIT();
    CP_WAIT0();
    FENCE_ASYNC();
    __syncthreads();

    uint32_t tmem;
    asm volatile("ld.shared.b32 %0, [%1];" : "=r"(tmem) : "r"(sbase + PW_PTR));

    if (wid == 0 && elect_one()) {
        uint64_t ad = MK_DESC(sbase + PW_A);
        uint64_t bd = MK_DESC(sbase + PW_WT);
        #pragma unroll
        for (int ks = 0; ks < 16; ks++) {
            uint64_t oa = (uint64_t)((ks >> 2) * 1024 + (ks & 3) * 2);
            uint64_t ob = (uint64_t)((ks >> 2) * 2048 + (ks & 3) * 2);
            uint32_t en = ks > 0 ? 1u : 0u;
            mma_bf16_n128(tmem + 0,   ad + oa, bd + ob,        en);
            mma_bf16_n128(tmem + 128, ad + oa, bd + ob + 1024, en);
        }
        TC_COMMIT(sbase + PW_MB);
    }
    __syncthreads();
    MBAR_WAIT(sbase + PW_MB, 0u);
    TC_FENCE_AFTER();

    uint32_t* stage = (uint32_t*)smem;
    #pragma unroll 1
    for (int cb = 0; cb < 8; cb++) {
        uint32_t r[32];
        LDTM32(r, tmem + cb * 32);
        TC_WAIT_LD();
        #pragma unroll
        for (int j = 0; j < 16; j++)
            stage[tid * 132 + cb * 16 + j] =
                pack_bf16x2(__uint_as_float(r[2 * j]), __uint_as_float(r[2 * j + 1]));
    }
    __syncthreads();
    uint32_t* gout = g_pw + (size_t)m0 * 128;
    #pragma unroll 8
    for (int i = 0; i < 128; i++) {
        int idx = tid + i * 128;
        gout[idx] = stage[(idx >> 7) * 132 + (idx & 127)];
    }
    __syncthreads();
    if (tid == 0) MBAR_INVAL(sbase + PW_MB);
    __syncthreads();
    if (wid == 0) TC_DEALLOC(tmem, 256);
#else
    for (int n = tid; n < D; n += 128) {
        int row = m0;
        float2 a0 = unpack_bf(g_sy[(size_t)row * 128]);
        float2 w0 = unpack_bf(g_wt[n * 128]);
        g_pw[(size_t)row * 128 + n / 2] = pack_bf16x2(a0.x * w0.x, a0.y * w0.y);
    }
#endif
}

// ---------------- kernel 4: warp-specialized fused kernel, PAIR pipeline ------
// (R9 structure; producer loads via cp.async)
#define F_P     0u
#define F_Q     65536u
#define F_S     131072u      // 2 x 32768 (subtile A, subtile B)
#define F_SSQ   196608u      // 2048 f32
#define F_SMK   204800u      // 2048 f32
#define F_ANYV  212992u      // 32 u32
#define F_ALLV  213120u      // 32 u32
#define F_MODE  213248u
#define F_PTR   213260u
#define F_MBF   213264u      // full[2]
#define F_MBE   213280u      // empty[2]
#define F_CMB   213296u      // 2*256 f32 (Z, Nv)
#define F_SMEM  215344

#define MODE_FAST 0
#define MODE_UNIF 1
#define MODE_GEN  2

__global__ void __launch_bounds__(384, 1) fused_kernel(
    const float* __restrict__ xmask, const float* __restrict__ ymask) {
    extern __shared__ char smem[];
    int tid = threadIdx.x;
    int b = blockIdx.x >> 4;
    int p0 = (blockIdx.x & 15) * 128;
#if defined(__CUDA_ARCH_SPECIFIC__)
    uint32_t sbase = smem_u32(smem);
    int wid = tid >> 5;
    int lane = tid & 31;

    if (wid == 0) { TC_ALLOC(sbase + F_PTR, 512); TC_RELINQ(); }
    if (tid == 0) {
        #pragma unroll
        for (int k = 0; k < 2; k++) {
            MBAR_INIT(sbase + F_MBF + k * 8, 1);   // full: 1 commit per pair
            MBAR_INIT(sbase + F_MBE + k * 8, 8);   // empty: 1 arrive per consumer warp
        }
    }

    float* s_ssq  = (float*)(smem + F_SSQ);
    float* s_smk  = (float*)(smem + F_SMK);
    uint32_t* s_anyv = (uint32_t*)(smem + F_ANYV);
    uint32_t* s_allv = (uint32_t*)(smem + F_ALLV);
    uint32_t* s_mode = (uint32_t*)(smem + F_MODE);

    for (int i = tid; i < L; i += 384) {
        s_ssq[i] = g_src_sq[b * L + i];
        s_smk[i] = xmask[b * L + i];
    }
    int cnt = __syncthreads_count((tid < 128) ? (ymask[b * L + p0 + tid] != 0.f) : 0);
    if (tid < 32) {
        float fa = 0.f, fl = 1.f;
        #pragma unroll 8
        for (int i = 0; i < 64; i++) {
            float v = s_smk[tid * 64 + i];
            fa = fmaxf(fa, v);
            fl = fminf(fl, (v != 0.f) ? 1.f : 0.f);
        }
        s_anyv[tid] = (fa != 0.f) ? 1u : 0u;
        s_allv[tid] = (fl != 0.f) ? 1u : 0u;
        unsigned anyb = __ballot_sync(0xffffffffu, fa != 0.f);
        if (tid == 0)
            s_mode[0] = (cnt == 0 || anyb == 0) ? MODE_UNIF
                       : (cnt == 128 ? MODE_FAST : MODE_GEN);
    }
    __syncthreads();
    uint32_t mode = s_mode[0];

    load_tile_cp(g_sy + ((size_t)b * L + p0) * 128, sbase, F_P, tid, 384, 128);
    if (mode != MODE_UNIF)
        load_tile_cp(g_pw + ((size_t)b * L + p0) * 128, sbase, F_Q, tid, 384, 128);
    CP_COMMIT();
    CP_WAIT0();
    FENCE_ASYNC();
    __syncthreads();

    uint32_t tmem;
    asm volatile("ld.shared.b32 %0, [%1];" : "=r"(tmem) : "r"(sbase + F_PTR));

    if (tid < 256) {
        // ---------------- consumers (8 warps) ----------------
        int sp = wid & 3;
        int half = wid >> 2;
        int row = sp * 32 + lane;
        float psq = g_pred_sq[b * L + p0 + row];
        float pm  = ymask[b * L + p0 + row];
        bool pmz = (pm == 0.f);
        float Z = 0.f, Nv = 0.f;

        int it = 0;
        #pragma unroll 1
        for (int jp = 0; jp < 16; jp++) {
            if (mode == MODE_FAST && !(s_anyv[2 * jp] | s_anyv[2 * jp + 1])) continue;
            MBAR_WAIT(sbase + F_MBF + (uint32_t)(it & 1) * 8, (uint32_t)((it >> 1) & 1));
            TC_FENCE_AFTER();
            uint32_t pb = tmem + (uint32_t)(it & 1) * 256u;
            if (mode == MODE_UNIF) {
                uint32_t c0[32], c1[32];
                LDTM32(c0, pb + (uint32_t)(half * 64));
                LDTM32(c1, pb + (uint32_t)(half * 64 + 32));
                TC_WAIT_LD();
                if (lane == 0) MBAR_ARRIVE(sbase + F_MBE + (uint32_t)(it & 1) * 8);
                int sb0 = jp * 128 + half * 64;
                float na[4] = {0.f, 0.f, 0.f, 0.f};
                #pragma unroll
                for (int jj = 0; jj < 32; jj++) {
                    float d2 = fmaxf(fmaf(-2.f, __uint_as_float(c0[jj]),
                                          psq + s_ssq[sb0 + jj]), 0.f);
                    na[jj & 3] += sqrt_fast(d2);
                }
                #pragma unroll
                for (int jj = 0; jj < 32; jj++) {
                    float d2 = fmaxf(fmaf(-2.f, __uint_as_float(c1[jj]),
                                          psq + s_ssq[sb0 + 32 + jj]), 0.f);
                    na[jj & 3] += sqrt_fast(d2);
                }
                Nv += (na[0] + na[1]) + (na[2] + na[3]);
            } else {
                #pragma unroll 1
                for (int h2 = 0; h2 < 2; h2++) {
                    int j = 2 * jp + h2;
                    uint32_t sbb = pb + (uint32_t)(h2 * 128 + half * 32);
                    uint32_t cxr[32], trr[32];
                    LDTM32(cxr, sbb);
                    LDTM32(trr, sbb + 64u);
                    TC_WAIT_LD();
                    if (h2 == 1 && lane == 0)
                        MBAR_ARRIVE(sbase + F_MBE + (uint32_t)(it & 1) * 8);
                    int sb0 = j * 64 + half * 32;
                    float za[4] = {0.f, 0.f, 0.f, 0.f}, na[4] = {0.f, 0.f, 0.f, 0.f};
                    if (mode == MODE_FAST && s_allv[j]) {
                        #pragma unroll
                        for (int jj = 0; jj < 32; jj++) {
                            float d2 = fmaxf(fmaf(-2.f, __uint_as_float(cxr[jj]),
                                                  psq + s_ssq[sb0 + jj]), 0.f);
                            float cc = sqrt_fast(d2);
                            float e = ex2_fast(fminf(__uint_as_float(trr[jj]), 100.f));
                            za[jj & 3] += e;
                            na[jj & 3] = fmaf(e, cc, na[jj & 3]);
                        }
                    } else {
                        #pragma unroll
                        for (int jj = 0; jj < 32; jj++) {
                            float d2 = fmaxf(fmaf(-2.f, __uint_as_float(cxr[jj]),
                                                  psq + s_ssq[sb0 + jj]), 0.f);
                            float cc = sqrt_fast(d2);
                            float e = ex2_fast(fminf(__uint_as_float(trr[jj]), 100.f));
                            e = (s_smk[sb0 + jj] != 0.f) ? e : 0.f;
                            e = pmz ? 1.f : e;
                            za[jj & 3] += e;
                            na[jj & 3] = fmaf(e, cc, na[jj & 3]);
                        }
                    }
                    Z  += (za[0] + za[1]) + (za[2] + za[3]);
                    Nv += (na[0] + na[1]) + (na[2] + na[3]);
                }
            }
            it++;
        }
        if (mode == MODE_UNIF) Z = 1024.f;   // 64 cols x 16 pairs per warp
        float* cm = (float*)(smem + F_CMB);
        cm[tid] = Z; cm[256 + tid] = Nv;
    } else {
        // ---------------- producers (warps 8-11) ----------------
        int ptid = tid - 256;
        uint64_t pd = MK_DESC(sbase + F_P);
        uint64_t qd = MK_DESC(sbase + F_Q);
        int it = 0;
        #pragma unroll 1
        for (int jp = 0; jp < 16; jp++) {
            if (mode == MODE_FAST && !(s_anyv[2 * jp] | s_anyv[2 * jp + 1])) continue;
            // SMEM reuse: MMAs of previous pair must be done
            if (it >= 1)
                MBAR_WAIT(sbase + F_MBF + (uint32_t)((it - 1) & 1) * 8,
                          (uint32_t)(((it - 1) >> 1) & 1));
            load_tile_cp(g_sx + ((size_t)b * L + 2 * jp * 64) * 128, sbase,
                         F_S, ptid, 128, 64);
            load_tile_cp(g_sx + ((size_t)b * L + (2 * jp + 1) * 64) * 128, sbase,
                         F_S + 32768u, ptid, 128, 64);
            CP_COMMIT();
            CP_WAIT0();
            FENCE_ASYNC();
            asm volatile("bar.sync 1, 128;" ::: "memory");
            if (wid == 8) {
                // TMEM pair-buffer reuse: consumers drained pair it-2
                if (it >= 2)
                    MBAR_WAIT(sbase + F_MBE + (uint32_t)(it & 1) * 8,
                              (uint32_t)(((it >> 1) - 1) & 1));
                if (elect_one()) {
                    uint64_t sdA = MK_DESC(sbase + F_S);
                    uint64_t sdB = MK_DESC(sbase + F_S + 32768u);
                    uint32_t pb = tmem + (uint32_t)(it & 1) * 256u;
                    if (mode == MODE_UNIF) {
                        #pragma unroll
                        for (int ks = 0; ks < 16; ks++) {
                            uint64_t oa = (uint64_t)((ks >> 2) * 1024 + (ks & 3) * 2);
                            uint64_t ob = (uint64_t)((ks >> 2) * 512 + (ks & 3) * 2);
                            uint32_t en = ks > 0 ? 1u : 0u;
                            mma_bf16_n64(pb + 0,  pd + oa, sdA + ob, en);
                            mma_bf16_n64(pb + 64, pd + oa, sdB + ob, en);
                        }
                    } else {
                        #pragma unroll
                        for (int ks = 0; ks < 16; ks++) {
                            uint64_t oa = (uint64_t)((ks >> 2) * 1024 + (ks & 3) * 2);
                            uint64_t ob = (uint64_t)((ks >> 2) * 512 + (ks & 3) * 2);
                            uint32_t en = ks > 0 ? 1u : 0u;
                            mma_bf16_n64(pb + 0,   pd + oa, sdA + ob, en);
                            mma_bf16_n64(pb + 64,  qd + oa, sdA + ob, en);
                            mma_bf16_n64(pb + 128, pd + oa, sdB + ob, en);
                            mma_bf16_n64(pb + 192, qd + oa, sdB + ob, en);
                        }
                    }
                    TC_COMMIT(sbase + F_MBF + (uint32_t)(it & 1) * 8);
                }
            }
            it++;
        }
    }
    __syncthreads();

    // combine halves: row r partials at cm[r] and cm[r+128]
    if (tid < 128) {
        float* cm = (float*)(smem + F_CMB);
        float Zt = cm[tid] + cm[tid + 128];
        float Nt = cm[256 + tid] + cm[256 + tid + 128];
        g_rowval[b * L + p0 + tid] = Nt / Zt;
    }
    __syncthreads();
    if (tid == 0) {
        #pragma unroll
        for (int k = 0; k < 2; k++) {
            MBAR_INVAL(sbase + F_MBF + k * 8);
            MBAR_INVAL(sbase + F_MBE + k * 8);
        }
    }
    __syncthreads();
    if (wid == 0) TC_DEALLOC(tmem, 512);
#else
    // dead generic-PTX fallback (GB300 always loads the sm_103a cubin)
    if (tid < 128) {
        int p = p0 + tid;
        float psq = g_pred_sq[b * L + p];
        float pm  = ymask[b * L + p];
        float Z = 0.f, Nv = 0.f;
        for (int s = 0; s < L; s++) {
            float cross = 0.f, tvv = 0.f;
            for (int kk = 0; kk < 128; kk++) {
                float2 a = unpack_bf(g_sy[((size_t)b * L + p) * 128 + kk]);
                float2 qv = unpack_bf(g_pw[((size_t)b * L + p) * 128 + kk]);
                float2 s2 = unpack_bf(g_sx[((size_t)b * L + s) * 128 + kk]);
                cross += a.x * s2.x + a.y * s2.y;
                tvv += qv.x * s2.x + qv.y * s2.y;
            }
            float c = sqrtf(fmaxf(psq + g_src_sq[b * L + s] - 2.f * cross, 0.f));
            float e;
            if (pm == 0.f) e = 1.f;
            else e = (xmask[b * L + s] != 0.f) ? exp2f(fminf(tvv, 100.f)) : 0.f;
            Z += e;
            Nv += e * c;
        }
        g_rowval[b * L + p] = Nv / Z;
    }
#endif
}

// ---------------- kernel 5: deterministic final reduction ----------------
__global__ void finalize_kernel(const float* __restrict__ xmask,
                                const float* __restrict__ ymask,
                                float* __restrict__ out) {
    __shared__ float red[256];
    __shared__ float inv[B];
    int tid = threadIdx.x;
    int warp = tid >> 5;
    int lane = tid & 31;
    float n1 = 0.f, n2 = 0.f;
    for (int i = lane; i < L; i += 32) {
        n1 += ymask[warp * L + i];
        n2 += xmask[warp * L + i];
    }
    #pragma unroll
    for (int o = 16; o > 0; o >>= 1) {
        n1 += __shfl_down_sync(0xffffffffu, n1, o);
        n2 += __shfl_down_sync(0xffffffffu, n2, o);
    }
    if (lane == 0) inv[warp] = 1.f / (n1 * n2);

    float s = 0.f;
    for (int i = tid; i < B * L; i += 256) s += g_rowval[i];
    red[tid] = s;
    __syncthreads();
    for (int o = 128; o > 0; o >>= 1) {
        if (tid < o) red[tid] += red[tid + o];
        __syncthreads();
    }
    if (tid == 0) {
        float F = 0.f;
        for (int bb = 0; bb < B; bb++) F += inv[bb];
        out[0] = red[0] * F / (float)(B * B);
    }
}

// ---------------- launch ----------------
extern "C" void kernel_launch(void* const* d_in, const int* in_sizes, int n_in,
                              void* d_out, int out_size) {
    const float* hx = (const float*)d_in[0];
    const float* hy = (const float*)d_in[1];
    const float* xm = (const float*)d_in[2];
    const float* ym = (const float*)d_in[3];
    const float* W  = (const float*)d_in[4];
    float* out = (float*)d_out;

    cudaFuncSetAttribute(predw_kernel,
                         cudaFuncAttributeMaxDynamicSharedMemorySize, PW_SMEM);
    cudaFuncSetAttribute(fused_kernel,
                         cudaFuncAttributeMaxDynamicSharedMemorySize, F_SMEM);

    prep_kernel<<<(B * L * 32 + 255) / 256, 256>>>(hx, hy);
    wt_kernel<<<D, 128>>>(W);
    predw_kernel<<<(B * L) / 128, 128, PW_SMEM>>>();
    fused_kernel<<<B * (L / 128), 384, F_SMEM>>>(xm, ym);
    finalize_kernel<<<1, 256>>>(xm, ym, out);
}

// round 14
// speedup vs baseline: 1.4380x; 1.0005x over previous
#include <cuda_runtime.h>
#include <cuda_bf16.h>
#include <math.h>
#include <cstdint>

#define B 8
#define L 2048
#define D 256
#define NEG_INF -1e10f

// ---------------- device scratch (static, no allocations) ----------------
__device__ __align__(16) uint32_t g_sx[B * L * D / 2];   // hx bf16x2 packed, row-major
__device__ __align__(16) uint32_t g_sy[B * L * D / 2];   // hy bf16x2
__device__ __align__(16) uint32_t g_wt[D * D / 2];       // (log2e * W)^T [n][k] bf16x2
__device__ __align__(16) uint32_t g_pw[B * L * D / 2];   // predW bf16x2 (log2 domain)
__device__ float g_pred_sq[B * L];
__device__ float g_src_sq[B * L];
__device__ float g_rowval[B * L];

// ---------------- generic helpers ----------------
__device__ __forceinline__ uint32_t smem_u32(const void* p) {
    uint32_t a;
    asm("{ .reg .u64 t; cvta.to.shared.u64 t, %1; cvt.u32.u64 %0, t; }" : "=r"(a) : "l"(p));
    return a;
}
__device__ __forceinline__ uint32_t pack_bf16x2(float lo, float hi) {
    uint32_t u;
    asm("cvt.rn.bf16x2.f32 %0, %1, %2;" : "=r"(u) : "f"(hi), "f"(lo));
    return u;
}
__device__ __forceinline__ float2 unpack_bf(uint32_t u) {
    __nv_bfloat162 h = *reinterpret_cast<__nv_bfloat162*>(&u);
    return make_float2(__bfloat162float(h.x), __bfloat162float(h.y));
}
__device__ __forceinline__ float sqrt_fast(float v) {
    float r;
    asm("sqrt.approx.f32 %0, %1;" : "=f"(r) : "f"(v));
    return r;
}
__device__ __forceinline__ float ex2_fast(float v) {
    float r;
    asm("ex2.approx.f32 %0, %1;" : "=f"(r) : "f"(v));
    return r;
}

// ---- cp.async 16B into swizzled smem ----
__device__ __forceinline__ void cp16(uint32_t saddr, const void* gptr) {
    asm volatile("cp.async.cg.shared.global [%0], [%1], 16;"
                 :: "r"(saddr), "l"(gptr) : "memory");
}
#define CP_COMMIT() asm volatile("cp.async.commit_group;" ::: "memory")
#define CP_WAIT0()  asm volatile("cp.async.wait_group 0;" ::: "memory")
#define CP_WAIT1()  asm volatile("cp.async.wait_group 1;" ::: "memory")

// Async-load a [nrows x 256] bf16 tile into SW128 blocked-atom smem (no wait).
__device__ __forceinline__ void load_tile_cp(const uint32_t* __restrict__ g,
                                             uint32_t sm_u32, uint32_t off,
                                             int tid, int nthr, int nrows) {
    const uint4* g4 = (const uint4*)g;
    int total = nrows * 32;            // uint4 per tile
    int ar = nrows >> 3;               // atom-rows
    for (int idx = tid; idx < total; idx += nthr) {
        int r = idx >> 5;
        uint32_t kb = (uint32_t)(idx & 31) * 16u;
        uint32_t boff = (uint32_t)((r >> 3) + (int)(kb >> 7) * ar) * 1024u
                        + (uint32_t)(r & 7) * 128u + (kb & 127u);
        uint32_t sw = boff ^ ((boff >> 3) & 0x70);
        cp16(sm_u32 + off + sw, g4 + idx);
    }
}

// ---------------- kernel 1: prep — bf16 convert + fp32 sq-norms ----------------
__global__ void prep_kernel(const float* __restrict__ hx, const float* __restrict__ hy) {
    int gtid = blockIdx.x * blockDim.x + threadIdx.x;
    int row = gtid >> 5;
    int lane = gtid & 31;
    if (row >= B * L) return;
    const float2* xr = (const float2*)(hx + (size_t)row * D);
    const float2* yr = (const float2*)(hy + (size_t)row * D);
    uint32_t* xo = g_sx + (size_t)row * 128;
    uint32_t* yo = g_sy + (size_t)row * 128;
    float sx = 0.f, sy = 0.f;
    #pragma unroll
    for (int j = 0; j < 4; j++) {
        int c = j * 32 + lane;
        float2 vx = xr[c];
        sx += vx.x * vx.x + vx.y * vx.y;
        xo[c] = pack_bf16x2(vx.x, vx.y);
        float2 vy = yr[c];
        sy += vy.x * vy.x + vy.y * vy.y;
        yo[c] = pack_bf16x2(vy.x, vy.y);
    }
    #pragma unroll
    for (int o = 16; o > 0; o >>= 1) {
        sx += __shfl_down_sync(0xffffffffu, sx, o);
        sy += __shfl_down_sync(0xffffffffu, sy, o);
    }
    if (lane == 0) { g_src_sq[row] = sx; g_pred_sq[row] = sy; }
}

// ---------------- kernel 2: W transpose -> bf16 [n][k], scaled by log2(e) ------
__global__ void wt_kernel(const float* __restrict__ W) {
    const float LOG2E = 1.4426950408889634f;
    int n = blockIdx.x;
    int t = threadIdx.x;
    float a = W[(size_t)(2 * t) * D + n] * LOG2E;
    float b = W[(size_t)(2 * t + 1) * D + n] * LOG2E;
    g_wt[n * 128 + t] = pack_bf16x2(a, b);
}

// ---------------- tcgen05 machinery (sm_103a-only) ----------------
static constexpr uint64_t DESC_BASE_SW128 =
    (uint64_t(2) << 61) | (uint64_t(1) << 46) | (uint64_t(64) << 32) | (uint64_t(1) << 16);
#define MK_DESC(a) (DESC_BASE_SW128 | ((uint64_t)((a) >> 4) & 0x3FFF))
static constexpr uint32_t IDESC_BF16_N128 =
    (1u << 4) | (1u << 7) | (1u << 10) | (16u << 17) | (8u << 24);
static constexpr uint32_t IDESC_BF16_N64 =
    (1u << 4) | (1u << 7) | (1u << 10) | (8u << 17) | (8u << 24);

#if defined(__CUDA_ARCH_SPECIFIC__)
#define TC_ALLOC(sm, n)   asm volatile("tcgen05.alloc.cta_group::1.sync.aligned.shared::cta.b32 [%0], %1;" :: "r"(sm), "r"(n) : "memory")
#define TC_DEALLOC(t, n)  asm volatile("tcgen05.dealloc.cta_group::1.sync.aligned.b32 %0, %1;" :: "r"(t), "r"(n))
#define TC_RELINQ()       asm volatile("tcgen05.relinquish_alloc_permit.cta_group::1.sync.aligned;")
#define TC_COMMIT(mb)     asm volatile("tcgen05.commit.cta_group::1.mbarrier::arrive::one.shared::cluster.b64 [%0];" :: "r"(mb) : "memory")
#define TC_FENCE_AFTER()  asm volatile("tcgen05.fence::after_thread_sync;" ::: "memory")
#define TC_WAIT_LD()      asm volatile("tcgen05.wait::ld.sync.aligned;" ::: "memory")
#define MBAR_INIT(mb, c)  asm volatile("mbarrier.init.shared.b64 [%0], %1;" :: "r"(mb), "r"(c) : "memory")
#define MBAR_INVAL(mb)    asm volatile("mbarrier.inval.shared.b64 [%0];" :: "r"(mb) : "memory")
#define MBAR_ARRIVE(mb)   asm volatile("mbarrier.arrive.shared.b64 _, [%0];" :: "r"(mb) : "memory")
#define FENCE_ASYNC()     asm volatile("fence.proxy.async.shared::cta;" ::: "memory")

#define MBAR_WAIT(mb, par) do {                                                        \
    uint32_t _m = (mb), _p = (par), _d;                                                \
    asm volatile("{\n\t.reg .pred p;\n\t"                                              \
        "mbarrier.try_wait.parity.acquire.cta.shared::cta.b64 p, [%1], %2;\n\t"        \
        "selp.b32 %0, 1, 0, p;\n\t}" : "=r"(_d) : "r"(_m), "r"(_p) : "memory");        \
    if (!_d) {                                                                          \
        asm volatile("{\n\t.reg .pred P1;\n\tWL_%=:\n\t"                               \
            "mbarrier.try_wait.parity.acquire.cta.shared::cta.b64 P1, [%0], %1, 0x989680;\n\t" \
            "@P1 bra.uni WD_%=;\n\tbra.uni WL_%=;\n\tWD_%=:\n\t}"                      \
            :: "r"(_m), "r"(_p) : "memory");                                            \
    } } while (0)

#define LDTM32(r, addr)                                                                \
    asm volatile("tcgen05.ld.sync.aligned.32x32b.x32.b32 "                             \
        "{%0,%1,%2,%3,%4,%5,%6,%7,%8,%9,%10,%11,%12,%13,%14,%15,"                      \
        "%16,%17,%18,%19,%20,%21,%22,%23,%24,%25,%26,%27,%28,%29,%30,%31}, [%32];"     \
        : "=r"((r)[0]),"=r"((r)[1]),"=r"((r)[2]),"=r"((r)[3]),                          \
          "=r"((r)[4]),"=r"((r)[5]),"=r"((r)[6]),"=r"((r)[7]),                          \
          "=r"((r)[8]),"=r"((r)[9]),"=r"((r)[10]),"=r"((r)[11]),                        \
          "=r"((r)[12]),"=r"((r)[13]),"=r"((r)[14]),"=r"((r)[15]),                      \
          "=r"((r)[16]),"=r"((r)[17]),"=r"((r)[18]),"=r"((r)[19]),                      \
          "=r"((r)[20]),"=r"((r)[21]),"=r"((r)[22]),"=r"((r)[23]),                      \
          "=r"((r)[24]),"=r"((r)[25]),"=r"((r)[26]),"=r"((r)[27]),                      \
          "=r"((r)[28]),"=r"((r)[29]),"=r"((r)[30]),"=r"((r)[31])                       \
        : "r"(addr))

__device__ __forceinline__ uint32_t elect_one() {
    uint32_t pred;
    asm volatile("{\n\t.reg .pred p;\n\telect.sync _|p, 0xFFFFFFFF;\n\tselp.b32 %0, 1, 0, p;\n\t}" : "=r"(pred));
    return pred;
}
__device__ __forceinline__ void mma_bf16_n128(uint32_t d, uint64_t a, uint64_t b, uint32_t en) {
    asm volatile(
        "{\n\t.reg .pred p;\n\tsetp.ne.u32 p, %4, 0;\n\t"
        "tcgen05.mma.cta_group::1.kind::f16 [%0], %1, %2, %3, {%5,%5,%5,%5}, p;\n\t}"
        :: "r"(d), "l"(a), "l"(b), "r"(IDESC_BF16_N128), "r"(en), "r"(0u)
        : "memory");
}
__device__ __forceinline__ void mma_bf16_n64(uint32_t d, uint64_t a, uint64_t b, uint32_t en) {
    asm volatile(
        "{\n\t.reg .pred p;\n\tsetp.ne.u32 p, %4, 0;\n\t"
        "tcgen05.mma.cta_group::1.kind::f16 [%0], %1, %2, %3, {%5,%5,%5,%5}, p;\n\t}"
        :: "r"(d), "l"(a), "l"(b), "r"(IDESC_BF16_N64), "r"(en), "r"(0u)
        : "memory");
}
#endif  // __CUDA_ARCH_SPECIFIC__

// ---------------- kernel 3: predW via tcgen05 ----------------
#define PW_A   0u
#define PW_WT  65536u
#define PW_PTR 196608u
#define PW_MB  196624u
#define PW_SMEM 196640

__global__ void __launch_bounds__(128, 1) predw_kernel() {
    extern __shared__ char smem[];
    int tid = threadIdx.x;
    int m0 = blockIdx.x * 128;
#if defined(__CUDA_ARCH_SPECIFIC__)
    uint32_t sbase = smem_u32(smem);
    int wid = tid >> 5;
    if (wid == 0) { TC_ALLOC(sbase + PW_PTR, 256); TC_RELINQ(); }
    if (tid == 0) MBAR_INIT(sbase + PW_MB, 1);

    load_tile_cp(g_sy + (size_t)m0 * 128, sbase, PW_A, tid, 128, 128);
    load_tile_cp(g_wt, sbase, PW_WT, tid, 128, 256);
    CP_COMMIT();
    CP_WAIT0();
    FENCE_ASYNC();
    __syncthreads();

    uint32_t tmem;
    asm volatile("ld.shared.b32 %0, [%1];" : "=r"(tmem) : "r"(sbase + PW_PTR));

    if (wid == 0 && elect_one()) {
        uint64_t ad = MK_DESC(sbase + PW_A);
        uint64_t bd = MK_DESC(sbase + PW_WT);
        #pragma unroll
        for (int ks = 0; ks < 16; ks++) {
            uint64_t oa = (uint64_t)((ks >> 2) * 1024 + (ks & 3) * 2);
            uint64_t ob = (uint64_t)((ks >> 2) * 2048 + (ks & 3) * 2);
            uint32_t en = ks > 0 ? 1u : 0u;
            mma_bf16_n128(tmem + 0,   ad + oa, bd + ob,        en);
            mma_bf16_n128(tmem + 128, ad + oa, bd + ob + 1024, en);
        }
        TC_COMMIT(sbase + PW_MB);
    }
    __syncthreads();
    MBAR_WAIT(sbase + PW_MB, 0u);
    TC_FENCE_AFTER();

    uint32_t* stage = (uint32_t*)smem;
    #pragma unroll 1
    for (int cb = 0; cb < 8; cb++) {
        uint32_t r[32];
        LDTM32(r, tmem + cb * 32);
        TC_WAIT_LD();
        #pragma unroll
        for (int j = 0; j < 16; j++)
            stage[tid * 132 + cb * 16 + j] =
                pack_bf16x2(__uint_as_float(r[2 * j]), __uint_as_float(r[2 * j + 1]));
    }
    __syncthreads();
    uint32_t* gout = g_pw + (size_t)m0 * 128;
    #pragma unroll 8
    for (int i = 0; i < 128; i++) {
        int idx = tid + i * 128;
        gout[idx] = stage[(idx >> 7) * 132 + (idx & 127)];
    }
    __syncthreads();
    if (tid == 0) MBAR_INVAL(sbase + PW_MB);
    __syncthreads();
    if (wid == 0) TC_DEALLOC(tmem, 256);
#else
    for (int n = tid; n < D; n += 128) {
        int row = m0;
        float2 a0 = unpack_bf(g_sy[(size_t)row * 128]);
        float2 w0 = unpack_bf(g_wt[n * 128]);
        g_pw[(size_t)row * 128 + n / 2] = pack_bf16x2(a0.x * w0.x, a0.y * w0.y);
    }
#endif
}

// ---------------- kernel 4: warp-specialized fused kernel --------------------
// R10 sync skeleton (smem ring-2, TMEM ring-4 x 128 cols, commit per subtile,
// consumer waits per pair) + R12 cp.async loads + 1-subtile lookahead.
#define F_P     0u
#define F_Q     65536u
#define F_S     131072u      // 2 x 32768 smem ring (in-bounds: ends at 196608)
#define F_SSQ   196608u      // 2048 f32
#define F_SMK   204800u      // 2048 f32
#define F_ANYV  212992u      // 32 u32
#define F_ALLV  213120u      // 32 u32
#define F_MODE  213248u
#define F_PTR   213260u
#define F_MBF   213264u      // full[4]  (commit per subtile)
#define F_MBE   213296u      // empty[4] (1 arrive per consumer warp)
#define F_CMB   213328u      // 2*256 f32 (Z, Nv)
#define F_SMEM  215392

#define MODE_FAST 0
#define MODE_UNIF 1
#define MODE_GEN  2

__global__ void __launch_bounds__(384, 1) fused_kernel(
    const float* __restrict__ xmask, const float* __restrict__ ymask) {
    extern __shared__ char smem[];
    int tid = threadIdx.x;
    int b = blockIdx.x >> 4;
    int p0 = (blockIdx.x & 15) * 128;
#if defined(__CUDA_ARCH_SPECIFIC__)
    uint32_t sbase = smem_u32(smem);
    int wid = tid >> 5;
    int lane = tid & 31;

    if (wid == 0) { TC_ALLOC(sbase + F_PTR, 512); TC_RELINQ(); }
    if (tid == 0) {
        #pragma unroll
        for (int k = 0; k < 4; k++) {
            MBAR_INIT(sbase + F_MBF + k * 8, 1);   // full: 1 commit per subtile
            MBAR_INIT(sbase + F_MBE + k * 8, 8);   // empty: 1 arrive per consumer warp
        }
    }

    float* s_ssq  = (float*)(smem + F_SSQ);
    float* s_smk  = (float*)(smem + F_SMK);
    uint32_t* s_anyv = (uint32_t*)(smem + F_ANYV);
    uint32_t* s_allv = (uint32_t*)(smem + F_ALLV);
    uint32_t* s_mode = (uint32_t*)(smem + F_MODE);

    for (int i = tid; i < L; i += 384) {
        s_ssq[i] = g_src_sq[b * L + i];
        s_smk[i] = xmask[b * L + i];
    }
    int cnt = __syncthreads_count((tid < 128) ? (ymask[b * L + p0 + tid] != 0.f) : 0);
    if (tid < 32) {
        float fa = 0.f, fl = 1.f;
        #pragma unroll 8
        for (int i = 0; i < 64; i++) {
            float v = s_smk[tid * 64 + i];
            fa = fmaxf(fa, v);
            fl = fminf(fl, (v != 0.f) ? 1.f : 0.f);
        }
        s_anyv[tid] = (fa != 0.f) ? 1u : 0u;
        s_allv[tid] = (fl != 0.f) ? 1u : 0u;
        unsigned anyb = __ballot_sync(0xffffffffu, fa != 0.f);
        if (tid == 0)
            s_mode[0] = (cnt == 0 || anyb == 0) ? MODE_UNIF
                       : (cnt == 128 ? MODE_FAST : MODE_GEN);
    }
    __syncthreads();
    uint32_t mode = s_mode[0];

    load_tile_cp(g_sy + ((size_t)b * L + p0) * 128, sbase, F_P, tid, 384, 128);
    if (mode != MODE_UNIF)
        load_tile_cp(g_pw + ((size_t)b * L + p0) * 128, sbase, F_Q, tid, 384, 128);
    CP_COMMIT();
    CP_WAIT0();
    FENCE_ASYNC();
    __syncthreads();

    uint32_t tmem;
    asm volatile("ld.shared.b32 %0, [%1];" : "=r"(tmem) : "r"(sbase + F_PTR));

    if (tid < 256) {
        // ---------------- consumers (8 warps) — R10 structure ----------------
        int sp = wid & 3;
        int half = wid >> 2;
        int row = sp * 32 + lane;
        float psq = g_pred_sq[b * L + p0 + row];
        float pm  = ymask[b * L + p0 + row];
        bool pmz = (pm == 0.f);
        float Z = 0.f, Nv = 0.f;

        int k = 0;   // kept-pair counter
        #pragma unroll 1
        for (int jp = 0; jp < 16; jp++) {
            if (mode == MODE_FAST && !(s_anyv[2 * jp] | s_anyv[2 * jp + 1])) continue;
            int sA = 2 * k, sB = 2 * k + 1;           // subtile counters
            MBAR_WAIT(sbase + F_MBF + (uint32_t)(sB & 3) * 8, (uint32_t)((sB >> 2) & 1));
            TC_FENCE_AFTER();
            uint32_t bufA = tmem + (uint32_t)(sA & 3) * 128u + (uint32_t)(half * 32);
            uint32_t bufB = tmem + (uint32_t)(sB & 3) * 128u + (uint32_t)(half * 32);
            int jA = 2 * jp, jB = 2 * jp + 1;
            int sbA = jA * 64 + half * 32;
            int sbB = jB * 64 + half * 32;
            if (mode == MODE_UNIF) {
                uint32_t cA[32], cB[32];
                LDTM32(cA, bufA);
                LDTM32(cB, bufB);
                TC_WAIT_LD();
                if (lane == 0) {
                    MBAR_ARRIVE(sbase + F_MBE + (uint32_t)(sA & 3) * 8);
                    MBAR_ARRIVE(sbase + F_MBE + (uint32_t)(sB & 3) * 8);
                }
                float na[4] = {0.f, 0.f, 0.f, 0.f};
                #pragma unroll
                for (int jj = 0; jj < 32; jj++) {
                    float d2 = fmaxf(fmaf(-2.f, __uint_as_float(cA[jj]),
                                          psq + s_ssq[sbA + jj]), 0.f);
                    na[jj & 3] += sqrt_fast(d2);
                }
                #pragma unroll
                for (int jj = 0; jj < 32; jj++) {
                    float d2 = fmaxf(fmaf(-2.f, __uint_as_float(cB[jj]),
                                          psq + s_ssq[sbB + jj]), 0.f);
                    na[jj & 3] += sqrt_fast(d2);
                }
                Nv += (na[0] + na[1]) + (na[2] + na[3]);
            } else {
                uint32_t cxA[32], trA[32];
                LDTM32(cxA, bufA);
                LDTM32(trA, bufA + 64u);
                TC_WAIT_LD();
                if (lane == 0) MBAR_ARRIVE(sbase + F_MBE + (uint32_t)(sA & 3) * 8);
                // issue B's TMEM reads; math A overlaps their service
                uint32_t cxB[32], trB[32];
                LDTM32(cxB, bufB);
                LDTM32(trB, bufB + 64u);
                {   // math subtile A
                    float za[4] = {0.f, 0.f, 0.f, 0.f}, na[4] = {0.f, 0.f, 0.f, 0.f};
                    if (mode == MODE_FAST && s_allv[jA]) {
                        #pragma unroll
                        for (int jj = 0; jj < 32; jj++) {
                            float d2 = fmaxf(fmaf(-2.f, __uint_as_float(cxA[jj]),
                                                  psq + s_ssq[sbA + jj]), 0.f);
                            float cc = sqrt_fast(d2);
                            float e = ex2_fast(fminf(__uint_as_float(trA[jj]), 100.f));
                            za[jj & 3] += e;
                            na[jj & 3] = fmaf(e, cc, na[jj & 3]);
                        }
                    } else {
                        #pragma unroll
                        for (int jj = 0; jj < 32; jj++) {
                            float d2 = fmaxf(fmaf(-2.f, __uint_as_float(cxA[jj]),
                                                  psq + s_ssq[sbA + jj]), 0.f);
                            float cc = sqrt_fast(d2);
                            float e = ex2_fast(fminf(__uint_as_float(trA[jj]), 100.f));
                            e = (s_smk[sbA + jj] != 0.f) ? e : 0.f;
                            e = pmz ? 1.f : e;
                            za[jj & 3] += e;
                            na[jj & 3] = fmaf(e, cc, na[jj & 3]);
                        }
                    }
                    Z  += (za[0] + za[1]) + (za[2] + za[3]);
                    Nv += (na[0] + na[1]) + (na[2] + na[3]);
                }
                TC_WAIT_LD();
                if (lane == 0) MBAR_ARRIVE(sbase + F_MBE + (uint32_t)(sB & 3) * 8);
                {   // math subtile B
                    float za[4] = {0.f, 0.f, 0.f, 0.f}, na[4] = {0.f, 0.f, 0.f, 0.f};
                    if (mode == MODE_FAST && s_allv[jB]) {
                        #pragma unroll
                        for (int jj = 0; jj < 32; jj++) {
                            float d2 = fmaxf(fmaf(-2.f, __uint_as_float(cxB[jj]),
                                                  psq + s_ssq[sbB + jj]), 0.f);
                            float cc = sqrt_fast(d2);
                            float e = ex2_fast(fminf(__uint_as_float(trB[jj]), 100.f));
                            za[jj & 3] += e;
                            na[jj & 3] = fmaf(e, cc, na[jj & 3]);
                        }
                    } else {
                        #pragma unroll
                        for (int jj = 0; jj < 32; jj++) {
                            float d2 = fmaxf(fmaf(-2.f, __uint_as_float(cxB[jj]),
                                                  psq + s_ssq[sbB + jj]), 0.f);
                            float cc = sqrt_fast(d2);
                            float e = ex2_fast(fminf(__uint_as_float(trB[jj]), 100.f));
                            e = (s_smk[sbB + jj] != 0.f) ? e : 0.f;
                            e = pmz ? 1.f : e;
                            za[jj & 3] += e;
                            na[jj & 3] = fmaf(e, cc, na[jj & 3]);
                        }
                    }
                    Z  += (za[0] + za[1]) + (za[2] + za[3]);
                    Nv += (na[0] + na[1]) + (na[2] + na[3]);
                }
            }
            k++;
        }
        if (mode == MODE_UNIF) Z = 1024.f;   // 64 cols x 16 pairs per warp
        float* cm = (float*)(smem + F_CMB);
        cm[tid] = Z; cm[256 + tid] = Nv;
    } else {
        // ------- producers (warps 8-11), cp.async + 1-subtile lookahead -------
        int ptid = tid - 256;
        uint64_t pd = MK_DESC(sbase + F_P);
        uint64_t qd = MK_DESC(sbase + F_Q);

        // kept-subtile count (pairs kept together)
        int keep[16], nk = 0;
        #pragma unroll
        for (int jp = 0; jp < 16; jp++)
            if (!(mode == MODE_FAST && !(s_anyv[2 * jp] | s_anyv[2 * jp + 1])))
                keep[nk++] = jp;
        int total = nk * 2;

        // preload subtile 0 into smem buf 0
        if (total > 0) {
            int j0 = 2 * keep[0];
            load_tile_cp(g_sx + ((size_t)b * L + j0 * 64) * 128, sbase,
                         F_S, ptid, 128, 64);
            CP_COMMIT();
        }
        #pragma unroll 1
        for (int it = 0; it < total; it++) {
            if (it + 1 < total) {
                // smem buf (it+1)&1 last read by MMA(it-1) -> wait its commit
                if (it >= 1)
                    MBAR_WAIT(sbase + F_MBF + (uint32_t)((it - 1) & 3) * 8,
                              (uint32_t)(((it - 1) >> 2) & 1));
                int jn = 2 * keep[(it + 1) >> 1] + ((it + 1) & 1);
                load_tile_cp(g_sx + ((size_t)b * L + jn * 64) * 128, sbase,
                             F_S + (uint32_t)((it + 1) & 1) * 32768u, ptid, 128, 64);
                CP_COMMIT();
                CP_WAIT1();   // subtile it ready; it+1 in flight
            } else {
                CP_WAIT0();
            }
            FENCE_ASYNC();
            asm volatile("bar.sync 1, 128;" ::: "memory");
            if (wid == 8) {
                if (it >= 4)   // TMEM ring-4: consumers drained subtile it-4
                    MBAR_WAIT(sbase + F_MBE + (uint32_t)(it & 3) * 8,
                              (uint32_t)(((it >> 2) - 1) & 1));
                if (elect_one()) {
                    uint64_t sd = MK_DESC(sbase + F_S + (uint32_t)(it & 1) * 32768u);
                    uint32_t dbase = tmem + (uint32_t)(it & 3) * 128u;
                    if (mode == MODE_UNIF) {
                        #pragma unroll
                        for (int ks = 0; ks < 16; ks++) {
                            uint64_t oa = (uint64_t)((ks >> 2) * 1024 + (ks & 3) * 2);
                            uint64_t ob = (uint64_t)((ks >> 2) * 512 + (ks & 3) * 2);
                            mma_bf16_n64(dbase, pd + oa, sd + ob, ks > 0 ? 1u : 0u);
                        }
                    } else {
                        #pragma unroll
                        for (int ks = 0; ks < 16; ks++) {
                            uint64_t oa = (uint64_t)((ks >> 2) * 1024 + (ks & 3) * 2);
                            uint64_t ob = (uint64_t)((ks >> 2) * 512 + (ks & 3) * 2);
                            uint32_t en = ks > 0 ? 1u : 0u;
                            mma_bf16_n64(dbase + 0,  pd + oa, sd + ob, en);
                            mma_bf16_n64(dbase + 64, qd + oa, sd + ob, en);
                        }
                    }
                    TC_COMMIT(sbase + F_MBF + (uint32_t)(it & 3) * 8);
                }
            }
        }
    }
    __syncthreads();

    // combine halves: row r partials at cm[r] and cm[r+128]
    if (tid < 128) {
        float* cm = (float*)(smem + F_CMB);
        float Zt = cm[tid] + cm[tid + 128];
        float Nt = cm[256 + tid] + cm[256 + tid + 128];
        g_rowval[b * L + p0 + tid] = Nt / Zt;
    }
    __syncthreads();
    if (tid == 0) {
        #pragma unroll
        for (int k2 = 0; k2 < 4; k2++) {
            MBAR_INVAL(sbase + F_MBF + k2 * 8);
            MBAR_INVAL(sbase + F_MBE + k2 * 8);
        }
    }
    __syncthreads();
    if (wid == 0) TC_DEALLOC(tmem, 512);
#else
    // dead generic-PTX fallback (GB300 always loads the sm_103a cubin)
    if (tid < 128) {
        int p = p0 + tid;
        float psq = g_pred_sq[b * L + p];
        float pm  = ymask[b * L + p];
        float Z = 0.f, Nv = 0.f;
        for (int s = 0; s < L; s++) {
            float cross = 0.f, tvv = 0.f;
            for (int kk = 0; kk < 128; kk++) {
                float2 a = unpack_bf(g_sy[((size_t)b * L + p) * 128 + kk]);
                float2 qv = unpack_bf(g_pw[((size_t)b * L + p) * 128 + kk]);
                float2 s2 = unpack_bf(g_sx[((size_t)b * L + s) * 128 + kk]);
                cross += a.x * s2.x + a.y * s2.y;
                tvv += qv.x * s2.x + qv.y * s2.y;
            }
            float c = sqrtf(fmaxf(psq + g_src_sq[b * L + s] - 2.f * cross, 0.f));
            float e;
            if (pm == 0.f) e = 1.f;
            else e = (xmask[b * L + s] != 0.f) ? exp2f(fminf(tvv, 100.f)) : 0.f;
            Z += e;
            Nv += e * c;
        }
        g_rowval[b * L + p] = Nv / Z;
    }
#endif
}

// ---------------- kernel 5: deterministic final reduction ----------------
__global__ void finalize_kernel(const float* __restrict__ xmask,
                                const float* __restrict__ ymask,
                                float* __restrict__ out) {
    __shared__ float red[256];
    __shared__ float inv[B];
    int tid = threadIdx.x;
    int warp = tid >> 5;
    int lane = tid & 31;
    float n1 = 0.f, n2 = 0.f;
    for (int i = lane; i < L; i += 32) {
        n1 += ymask[warp * L + i];
        n2 += xmask[warp * L + i];
    }
    #pragma unroll
    for (int o = 16; o > 0; o >>= 1) {
        n1 += __shfl_down_sync(0xffffffffu, n1, o);
        n2 += __shfl_down_sync(0xffffffffu, n2, o);
    }
    if (lane == 0) inv[warp] = 1.f / (n1 * n2);

    float s = 0.f;
    for (int i = tid; i < B * L; i += 256) s += g_rowval[i];
    red[tid] = s;
    __syncthreads();
    for (int o = 128; o > 0; o >>= 1) {
        if (tid < o) red[tid] += red[tid + o];
        __syncthreads();
    }
    if (tid == 0) {
        float F = 0.f;
        for (int bb = 0; bb < B; bb++) F += inv[bb];
        out[0] = red[0] * F / (float)(B * B);
    }
}

// ---------------- launch ----------------
extern "C" void kernel_launch(void* const* d_in, const int* in_sizes, int n_in,
                              void* d_out, int out_size) {
    const float* hx = (const float*)d_in[0];
    const float* hy = (const float*)d_in[1];
    const float* xm = (const float*)d_in[2];
    const float* ym = (const float*)d_in[3];
    const float* W  = (const float*)d_in[4];
    float* out = (float*)d_out;

    cudaFuncSetAttribute(predw_kernel,
                         cudaFuncAttributeMaxDynamicSharedMemorySize, PW_SMEM);
    cudaFuncSetAttribute(fused_kernel,
                         cudaFuncAttributeMaxDynamicSharedMemorySize, F_SMEM);

    prep_kernel<<<(B * L * 32 + 255) / 256, 256>>>(hx, hy);
    wt_kernel<<<D, 128>>>(W);
    predw_kernel<<<(B * L) / 128, 128, PW_SMEM>>>();
    fused_kernel<<<B * (L / 128), 384, F_SMEM>>>(xm, ym);
    finalize_kernel<<<1, 256>>>(xm, ym, out);
}